// round 2
// baseline (speedup 1.0000x reference)
#include <cuda_runtime.h>
#include <cstdint>

#define BB 32
#define NN 1024
#define WW 64
#define RR 4
#define EPSF 1e-5f

// ------------------- device scratch (no allocations allowed) ----------------
__device__ float g_wc[BB*NN];
__device__ float g_ww[BB*NN];
__device__ float g_mem_new[BB*NN*WW];
__device__ __align__(16) float2 g_uv[BB*NN*RR];   // (u, u*w) per (b,m,r)
__device__ float g_scal[BB*8];                    // c[0..3], d[0..3]
__device__ float g_fwd[BB*RR*NN];
__device__ float g_bwdP[8*BB*RR*NN];              // per-rowblock col partials
__device__ float g_rc[BB*RR*NN];

// ------------------- helpers ------------------------------------------------
__device__ __forceinline__ unsigned long long pack2(float x, float y){
    unsigned long long r; asm("mov.b64 %0, {%1, %2};" : "=l"(r) : "f"(x), "f"(y)); return r;
}
__device__ __forceinline__ void unpack2(unsigned long long p, float &x, float &y){
    asm("mov.b64 {%0, %1}, %2;" : "=f"(x), "=f"(y) : "l"(p));
}
__device__ __forceinline__ void fma2(unsigned long long &d, unsigned long long a, unsigned long long b){
    asm("fma.rn.f32x2 %0, %1, %2, %0;" : "+l"(d) : "l"(a), "l"(b));
}
__device__ __forceinline__ float softplusf(float x){
    return fmaxf(x, 0.0f) + log1pf(expf(-fabsf(x)));
}

// ------------------- kernel 1: write-content cosine softmax ------------------
__global__ void __launch_bounds__(1024) k_wcontent(const float* __restrict__ memory,
                                                   const float* __restrict__ wkeys,
                                                   const float* __restrict__ wstr) {
    __shared__ float s_key[WW];
    __shared__ float s_sharp[NN];
    __shared__ float s_red[33];
    __shared__ float s_kn, s_sp;
    int b = blockIdx.x, tid = threadIdx.x;
    if (tid < WW) s_key[tid] = wkeys[b*WW + tid];
    __syncthreads();
    if (tid == 0) {
        float ss = 0.f;
        for (int c = 0; c < WW; c++) ss += s_key[c]*s_key[c];
        s_kn = sqrtf(ss + EPSF);
        s_sp = softplusf(wstr[b]);
    }
    __syncthreads();
    int lane = tid & 31, wid = tid >> 5;
    float kn = s_kn, sp = s_sp;
    for (int t = 0; t < 32; t++) {
        int n = wid*32 + t;
        const float* mrow = memory + ((size_t)b*NN + n)*WW;
        float m0 = mrow[lane], m1 = mrow[lane+32];
        float dot = m0*s_key[lane] + m1*s_key[lane+32];
        float ssq = m0*m0 + m1*m1;
        for (int off = 16; off; off >>= 1) {
            dot += __shfl_down_sync(~0u, dot, off);
            ssq += __shfl_down_sync(~0u, ssq, off);
        }
        if (lane == 0) {
            float mn = sqrtf(ssq + EPSF);
            s_sharp[n] = dot / (kn*mn + EPSF) * sp;
        }
    }
    __syncthreads();
    float v = s_sharp[tid];
    float m = v;
    for (int off = 16; off; off >>= 1) m = fmaxf(m, __shfl_down_sync(~0u, m, off));
    if (lane == 0) s_red[wid] = m;
    __syncthreads();
    if (wid == 0) {
        float mm = s_red[lane];
        for (int off = 16; off; off >>= 1) mm = fmaxf(mm, __shfl_down_sync(~0u, mm, off));
        if (lane == 0) s_red[32] = mm;
    }
    __syncthreads();
    float e = expf(v - s_red[32]);
    float s = e;
    for (int off = 16; off; off >>= 1) s += __shfl_down_sync(~0u, s, off);
    __syncthreads();
    if (lane == 0) s_red[wid] = s;
    __syncthreads();
    if (wid == 0) {
        float ss = s_red[lane];
        for (int off = 16; off; off >>= 1) ss += __shfl_down_sync(~0u, ss, off);
        if (lane == 0) s_red[32] = ss;
    }
    __syncthreads();
    g_wc[b*NN + tid] = e / s_red[32];
}

// ------------------- kernel 2: usage / allocation / write weights / scalars --
__global__ void __launch_bounds__(1024) k_alloc(const float* __restrict__ up,
                                                const float* __restrict__ wwp,
                                                const float* __restrict__ fg,
                                                const float* __restrict__ rwp,
                                                const float* __restrict__ p_prev,
                                                const float* __restrict__ ag_,
                                                const float* __restrict__ wg_) {
    __shared__ unsigned long long s_sk[NN];
    __shared__ float s_v[NN];
    __shared__ float s_alloc[NN];
    __shared__ float s_red[32][8];
    int b = blockIdx.x, i = threadIdx.x;

    float u0 = up[b*NN + i];
    float w0 = wwp[b*NN + i];
    float usage = u0 + (1.f - u0)*w0;
    float phi = 1.f;
    float uu[RR];
    #pragma unroll
    for (int r = 0; r < RR; r++) {
        float rw = rwp[(b*RR + r)*NN + i];
        uu[r] = rw;
        phi *= (1.f - fg[b*RR + r]*rw);
    }
    usage *= phi;
    float nu = 1.f - usage;   // in (0,1] -> positive float bits order-preserving
    s_sk[i] = ((unsigned long long)__float_as_uint(nu) << 10) | (unsigned int)(NN - 1 - i);
    __syncthreads();

    // bitonic sort descending; ties -> smaller original index first (top_k)
    for (int k = 2; k <= NN; k <<= 1)
        for (int j = k >> 1; j > 0; j >>= 1) {
            int ixj = i ^ j;
            if (ixj > i) {
                unsigned long long a = s_sk[i], c = s_sk[ixj];
                bool desc = ((i & k) == 0);
                if (desc ? (a < c) : (a > c)) { s_sk[i] = c; s_sk[ixj] = a; }
            }
            __syncthreads();
        }

    unsigned long long key = s_sk[i];
    float snu = __uint_as_float((unsigned int)(key >> 10));
    int oidx = (NN - 1) - (int)(key & (NN - 1));
    s_v[i] = 1.f - snu;            // sorted usage (ascending)
    __syncthreads();
    // inclusive product scan (Hillis-Steele)
    for (int off = 1; off < NN; off <<= 1) {
        float t = (i >= off) ? s_v[i - off] : 1.0f;
        __syncthreads();
        s_v[i] *= t;
        __syncthreads();
    }
    float excl = (i == 0) ? 1.0f : s_v[i - 1];
    s_alloc[oidx] = snu * excl;
    __syncthreads();

    float alloc = s_alloc[i];
    float ag = ag_[b], wg = wg_[b];
    float wc = g_wc[b*NN + i];
    float ww = wg * (ag*alloc + (1.f - ag)*wc);
    g_ww[b*NN + i] = ww;

    float p = p_prev[b*NN + i];
    float part[8];
    #pragma unroll
    for (int r = 0; r < RR; r++) {
        g_uv[(b*NN + i)*RR + r] = make_float2(uu[r], uu[r]*ww);
        part[r]     = uu[r]*p;    // c[r]
        part[4 + r] = uu[r]*ww;   // d[r]
    }
    int lane = i & 31, wid = i >> 5;
    #pragma unroll
    for (int j = 0; j < 8; j++)
        for (int off = 16; off; off >>= 1) part[j] += __shfl_down_sync(~0u, part[j], off);
    if (lane == 0)
        for (int j = 0; j < 8; j++) s_red[wid][j] = part[j];
    __syncthreads();
    if (wid == 0 && lane < 8) {
        float s = 0.f;
        for (int w = 0; w < 32; w++) s += s_red[w][lane];
        g_scal[b*8 + lane] = s;
    }
}

// ------------------- kernel 3: memory update --------------------------------
__global__ void __launch_bounds__(256) k_memnew(const float* __restrict__ memory,
                                                const float* __restrict__ erase,
                                                const float* __restrict__ wv) {
    int idx = blockIdx.x*blockDim.x + threadIdx.x;   // B*N*W/4 float4s
    int c4 = idx & 15;
    int n  = (idx >> 4) & (NN - 1);
    int b  = idx >> 14;
    float ww = g_ww[b*NN + n];
    float4 m = ((const float4*)memory)[idx];
    float4 e = ((const float4*)erase)[b*16 + c4];
    float4 v = ((const float4*)wv)[b*16 + c4];
    float4 o;
    o.x = m.x*(1.f - ww*e.x) + ww*v.x;
    o.y = m.y*(1.f - ww*e.y) + ww*v.y;
    o.z = m.z*(1.f - ww*e.z) + ww*v.z;
    o.w = m.w*(1.f - ww*e.w) + ww*v.w;
    ((float4*)g_mem_new)[idx] = o;
}

// ------------------- kernel 4: read-content cosine softmax (new memory) -----
__global__ void __launch_bounds__(1024) k_rcontent(const float* __restrict__ rkeys,
                                                   const float* __restrict__ rstr) {
    __shared__ float s_key[RR][WW];
    __shared__ float s_sharp[RR][NN];
    __shared__ float s_red[33];
    __shared__ float s_kn[RR], s_sp[RR];
    int b = blockIdx.x, tid = threadIdx.x;
    if (tid < RR*WW) s_key[tid/WW][tid%WW] = rkeys[b*RR*WW + tid];
    __syncthreads();
    if (tid < RR) {
        float ss = 0.f;
        for (int c = 0; c < WW; c++) ss += s_key[tid][c]*s_key[tid][c];
        s_kn[tid] = sqrtf(ss + EPSF);
        s_sp[tid] = softplusf(rstr[b*RR + tid]);
    }
    __syncthreads();
    int lane = tid & 31, wid = tid >> 5;
    for (int t = 0; t < 32; t++) {
        int n = wid*32 + t;
        const float* mrow = g_mem_new + ((size_t)b*NN + n)*WW;
        float m0 = mrow[lane], m1 = mrow[lane+32];
        float vals[5];
        vals[4] = m0*m0 + m1*m1;
        #pragma unroll
        for (int r = 0; r < RR; r++) vals[r] = m0*s_key[r][lane] + m1*s_key[r][lane+32];
        #pragma unroll
        for (int j = 0; j < 5; j++)
            for (int off = 16; off; off >>= 1) vals[j] += __shfl_down_sync(~0u, vals[j], off);
        if (lane == 0) {
            float mn = sqrtf(vals[4] + EPSF);
            #pragma unroll
            for (int r = 0; r < RR; r++)
                s_sharp[r][n] = vals[r] / (s_kn[r]*mn + EPSF) * s_sp[r];
        }
    }
    __syncthreads();
    for (int r = 0; r < RR; r++) {
        float v = s_sharp[r][tid];
        float m = v;
        for (int off = 16; off; off >>= 1) m = fmaxf(m, __shfl_down_sync(~0u, m, off));
        if (lane == 0) s_red[wid] = m;
        __syncthreads();
        if (wid == 0) {
            float mm = s_red[lane];
            for (int off = 16; off; off >>= 1) mm = fmaxf(mm, __shfl_down_sync(~0u, mm, off));
            if (lane == 0) s_red[32] = mm;
        }
        __syncthreads();
        float e = expf(v - s_red[32]);
        float s = e;
        for (int off = 16; off; off >>= 1) s += __shfl_down_sync(~0u, s, off);
        __syncthreads();
        if (lane == 0) s_red[wid] = s;
        __syncthreads();
        if (wid == 0) {
            float ss = s_red[lane];
            for (int off = 16; off; off >>= 1) ss += __shfl_down_sync(~0u, ss, off);
            if (lane == 0) s_red[32] = ss;
        }
        __syncthreads();
        g_rc[(b*RR + r)*NN + tid] = e / s_red[32];
        __syncthreads();
    }
}

// ------------------- kernel 5: fused link contraction (one pass over L) -----
// block = (b, rowblock of 128 rows). Loops 8 col-subtiles of 128.
// threads 0..127  : fwd (own one row, accumulate across all 1024 cols)
// threads 128..255: bwd (own one local col per subtile, 128-row partial)
__global__ void __launch_bounds__(256) k_link(const float* __restrict__ L) {
    extern __shared__ float smem[];
    float* s_L = smem;                              // 128*129 floats
    float2* s_uvr = (float2*)(smem + 128*129);      // 512 float2
    float2* s_uvc = s_uvr + 512;                    // 512 float2
    int b = blockIdx.x >> 3;
    int rb = blockIdx.x & 7;
    int n0 = rb * 128;
    int t = threadIdx.x;

    // uv for this block's rows (for bwd)
    ((float4*)s_uvr)[t] = ((const float4*)g_uv)[(size_t)(b*NN + n0)*2 + t];

    unsigned long long facc[RR] = {0ull,0ull,0ull,0ull};

    for (int s = 0; s < 8; s++) {
        __syncthreads();
        // load 128x128 subtile (coalesced float4), padded stride 129
        #pragma unroll
        for (int k = 0; k < 16; k++) {
            int q = k*256 + t;
            int row = q >> 5, c4 = q & 31;
            float4 v = ((const float4*)L)[(size_t)(b*NN + n0 + row)*256 + s*32 + c4];
            float* d = s_L + row*129 + c4*4;
            d[0] = v.x; d[1] = v.y; d[2] = v.z; d[3] = v.w;
        }
        // uv for this subtile's columns (for fwd)
        ((float4*)s_uvc)[t] = ((const float4*)g_uv)[(size_t)(b*NN + s*128)*2 + t];
        __syncthreads();

        if (t < 128) {
            const unsigned long long* uvc = (const unsigned long long*)s_uvc;
            const float* Lr = s_L + t*129;
            #pragma unroll 4
            for (int c = 0; c < 128; c++) {
                float Lv = Lr[c];
                unsigned long long LL = pack2(Lv, Lv);
                fma2(facc[0], LL, uvc[c*4+0]);
                fma2(facc[1], LL, uvc[c*4+1]);
                fma2(facc[2], LL, uvc[c*4+2]);
                fma2(facc[3], LL, uvc[c*4+3]);
            }
        } else {
            int c = t - 128;
            const unsigned long long* uvr = (const unsigned long long*)s_uvr;
            unsigned long long bacc[RR] = {0ull,0ull,0ull,0ull};
            #pragma unroll 4
            for (int m = 0; m < 128; m++) {
                float Lv = s_L[m*129 + c];
                unsigned long long LL = pack2(Lv, Lv);
                fma2(bacc[0], LL, uvr[m*4+0]);
                fma2(bacc[1], LL, uvr[m*4+1]);
                fma2(bacc[2], LL, uvr[m*4+2]);
                fma2(bacc[3], LL, uvr[m*4+3]);
            }
            int gcol = s*128 + c;
            float w = g_ww[b*NN + gcol];
            #pragma unroll
            for (int r = 0; r < RR; r++) {
                float A, Bv; unpack2(bacc[r], A, Bv);
                g_bwdP[(size_t)rb*(BB*RR*NN) + (size_t)(b*RR + r)*NN + gcol] = (1.f - w)*A - Bv;
            }
        }
    }

    if (t < 128) {
        int n = n0 + t;
        float w = g_ww[b*NN + n];
        #pragma unroll
        for (int r = 0; r < RR; r++) {
            float A, Bv; unpack2(facc[r], A, Bv);
            g_fwd[(size_t)(b*RR + r)*NN + n] = (1.f - w)*A - Bv + w*g_scal[b*8 + r];
        }
    }
}

// ------------------- kernel 6: combine read weights + read words ------------
__global__ void __launch_bounds__(256) k_out(const float* __restrict__ p_prev,
                                             const float* __restrict__ rmode,
                                             float* __restrict__ out) {
    __shared__ float s_rw[RR*NN];
    __shared__ float s_bm[RR], s_fm[RR], s_cm[RR];
    __shared__ float s_acc[4*RR*WW];
    int b = blockIdx.x, t = threadIdx.x;
    if (t < RR) {
        const float* rm = rmode + (b*RR + t)*3;
        float v0 = rm[0], v1 = rm[1], v2 = rm[2];
        float mx = fmaxf(v0, fmaxf(v1, v2));
        float e0 = expf(v0 - mx), e1 = expf(v1 - mx), e2 = expf(v2 - mx);
        float inv = 1.f / (e0 + e1 + e2);
        s_bm[t] = e0*inv; s_fm[t] = e1*inv; s_cm[t] = e2*inv;
    }
    __syncthreads();
    // phase 1: read weights for all (r, n)
    for (int j = 0; j < 16; j++) {
        int idx = j*256 + t;           // 0..4095
        int r = idx >> 10, n = idx & (NN - 1);
        float s = 0.f;
        #pragma unroll
        for (int rb2 = 0; rb2 < 8; rb2++)
            s += g_bwdP[(size_t)rb2*(BB*RR*NN) + (size_t)(b*RR + r)*NN + n];
        float bwd = s + p_prev[b*NN + n]*g_scal[b*8 + 4 + r];
        float rw = s_cm[r]*g_rc[(b*RR + r)*NN + n]
                 + s_fm[r]*g_fwd[(b*RR + r)*NN + n]
                 + s_bm[r]*bwd;
        s_rw[idx] = rw;
    }
    __syncthreads();
    // phase 2: read_words[r][c] = sum_n rw[r][n] * mem_new[n][c]
    int c = t & 63, sl = t >> 6;       // 4 slices of 256 n each
    float acc[RR] = {0.f, 0.f, 0.f, 0.f};
    for (int nn = 0; nn < 256; nn++) {
        int n = sl*256 + nn;
        float mv = g_mem_new[((size_t)b*NN + n)*WW + c];
        #pragma unroll
        for (int r = 0; r < RR; r++) acc[r] += s_rw[r*NN + n]*mv;
    }
    #pragma unroll
    for (int r = 0; r < RR; r++) s_acc[(sl*RR + r)*WW + c] = acc[r];
    __syncthreads();
    // t covers r(4) x c(64) = 256
    {
        int r = t >> 6, cc = t & 63;
        float s = 0.f;
        #pragma unroll
        for (int sl2 = 0; sl2 < 4; sl2++) s += s_acc[(sl2*RR + r)*WW + cc];
        out[(b*RR + r)*WW + cc] = s;
    }
}

// ------------------- launch -------------------------------------------------
extern "C" void kernel_launch(void* const* d_in, const int* in_sizes, int n_in,
                              void* d_out, int out_size) {
    const float* memory   = (const float*)d_in[0];
    const float* usage_p  = (const float*)d_in[1];
    const float* link_p   = (const float*)d_in[2];
    const float* prec_p   = (const float*)d_in[3];
    const float* rwp      = (const float*)d_in[4];
    const float* wwp      = (const float*)d_in[5];
    const float* rkeys    = (const float*)d_in[6];
    const float* rstr     = (const float*)d_in[7];
    const float* wkeys    = (const float*)d_in[8];
    const float* wstr     = (const float*)d_in[9];
    const float* erase    = (const float*)d_in[10];
    const float* wvec     = (const float*)d_in[11];
    const float* fgate    = (const float*)d_in[12];
    const float* agate    = (const float*)d_in[13];
    const float* wgate    = (const float*)d_in[14];
    const float* rmode    = (const float*)d_in[15];
    float* out = (float*)d_out;

    static bool attr_set = false;
    const int link_smem = (128*129)*4 + 512*8 + 512*8;   // 74240 bytes
    if (!attr_set) {
        cudaFuncSetAttribute(k_link, cudaFuncAttributeMaxDynamicSharedMemorySize, link_smem);
        attr_set = true;
    }

    k_wcontent<<<BB, 1024>>>(memory, wkeys, wstr);
    k_alloc<<<BB, 1024>>>(usage_p, wwp, fgate, rwp, prec_p, agate, wgate);
    k_memnew<<<(BB*NN*WW/4)/256, 256>>>(memory, erase, wvec);
    k_rcontent<<<BB, 1024>>>(rkeys, rstr);
    k_link<<<BB*8, 256, link_smem>>>(link_p);
    k_out<<<BB, 256>>>(prec_p, rmode, out);
}

// round 3
// speedup vs baseline: 1.6222x; 1.6222x over previous
#include <cuda_runtime.h>
#include <cstdint>

#define BB 32
#define NN 1024
#define WW 64
#define RR 4
#define EPSF 1e-5f

// ------------------- device scratch (no allocations allowed) ----------------
__device__ float g_wc[BB*NN];                     // write sharp (pre-softmax)
__device__ float g_ww[BB*NN];
__device__ float g_mem_new[BB*NN*WW];
__device__ __align__(16) float2 g_uv[BB*NN*RR];   // (u, u*w) per (b,m,r)
__device__ float g_scal[BB*8];                    // c[0..3], d[0..3]
__device__ float g_fwd[BB*RR*NN];
__device__ float g_bwdP[8*BB*RR*NN];              // per-rowblock col partials
__device__ float g_rc[BB*RR*NN];                  // read sharp (pre-softmax)

// ------------------- helpers ------------------------------------------------
__device__ __forceinline__ unsigned long long pack2(float x, float y){
    unsigned long long r; asm("mov.b64 %0, {%1, %2};" : "=l"(r) : "f"(x), "f"(y)); return r;
}
__device__ __forceinline__ void unpack2(unsigned long long p, float &x, float &y){
    asm("mov.b64 {%0, %1}, %2;" : "=f"(x), "=f"(y) : "l"(p));
}
__device__ __forceinline__ void fma2(unsigned long long &d, unsigned long long a, unsigned long long b){
    asm("fma.rn.f32x2 %0, %1, %2, %0;" : "+l"(d) : "l"(a), "l"(b));
}
__device__ __forceinline__ float softplusf(float x){
    return fmaxf(x, 0.0f) + log1pf(expf(-fabsf(x)));
}

// ------------------- kernel 1: write-key dots (sharp) ------------------------
// grid B*8, 128 threads; thread = one memory row.
__global__ void __launch_bounds__(128) k_wdot(const float* __restrict__ memory,
                                              const float* __restrict__ wkeys,
                                              const float* __restrict__ wstr) {
    __shared__ float s_key[WW];
    __shared__ float s_kn, s_sp;
    int b = blockIdx.x >> 3;
    int n0 = (blockIdx.x & 7) * 128;
    int t = threadIdx.x;
    if (t < WW) s_key[t] = wkeys[b*WW + t];
    __syncthreads();
    if (t == 0) {
        float ss = 0.f;
        #pragma unroll
        for (int c = 0; c < WW; c++) ss += s_key[c]*s_key[c];
        s_kn = sqrtf(ss + EPSF);
        s_sp = softplusf(wstr[b]);
    }
    __syncthreads();
    int n = n0 + t;
    const float4* row = (const float4*)(memory + ((size_t)(b*NN + n))*WW);
    float dot = 0.f, sq = 0.f;
    #pragma unroll
    for (int j = 0; j < 16; j++) {
        float4 v = row[j];
        dot += v.x*s_key[4*j] + v.y*s_key[4*j+1] + v.z*s_key[4*j+2] + v.w*s_key[4*j+3];
        sq  += v.x*v.x + v.y*v.y + v.z*v.z + v.w*v.w;
    }
    float mn = sqrtf(sq + EPSF);
    g_wc[b*NN + n] = dot / (s_kn*mn + EPSF) * s_sp;
}

// ------------------- kernel 2: softmax(wc) + usage + alloc + ww + scalars ---
__global__ void __launch_bounds__(1024) k_alloc(const float* __restrict__ up,
                                                const float* __restrict__ wwp,
                                                const float* __restrict__ fg,
                                                const float* __restrict__ rwp,
                                                const float* __restrict__ p_prev,
                                                const float* __restrict__ ag_,
                                                const float* __restrict__ wg_) {
    __shared__ unsigned long long s_sk[NN];
    __shared__ float s_alloc[NN];
    __shared__ float s_red[33];
    __shared__ float s_wp[32];
    __shared__ float s_red8[32][8];
    int b = blockIdx.x, i = threadIdx.x;
    int lane = i & 31, wid = i >> 5;

    // ---- write-content softmax (sharp -> wc), kept in register
    float sharp = g_wc[b*NN + i];
    float m = sharp;
    for (int off = 16; off; off >>= 1) m = fmaxf(m, __shfl_xor_sync(~0u, m, off));
    if (lane == 0) s_red[wid] = m;
    __syncthreads();
    if (wid == 0) {
        float mm = s_red[lane];
        for (int off = 16; off; off >>= 1) mm = fmaxf(mm, __shfl_xor_sync(~0u, mm, off));
        if (lane == 0) s_red[32] = mm;
    }
    __syncthreads();
    float e = expf(sharp - s_red[32]);
    float s = e;
    for (int off = 16; off; off >>= 1) s += __shfl_xor_sync(~0u, s, off);
    __syncthreads();
    if (lane == 0) s_red[wid] = s;
    __syncthreads();
    if (wid == 0) {
        float ss = s_red[lane];
        for (int off = 16; off; off >>= 1) ss += __shfl_xor_sync(~0u, ss, off);
        if (lane == 0) s_red[32] = ss;
    }
    __syncthreads();
    float wc = e / s_red[32];

    // ---- usage
    float u0 = up[b*NN + i];
    float w0 = wwp[b*NN + i];
    float usage = u0 + (1.f - u0)*w0;
    float phi = 1.f;
    float uu[RR];
    #pragma unroll
    for (int r = 0; r < RR; r++) {
        float rw = rwp[(b*RR + r)*NN + i];
        uu[r] = rw;
        phi *= (1.f - fg[b*RR + r]*rw);
    }
    usage *= phi;
    float nu = 1.f - usage;

    // ---- hybrid bitonic sort, descending (ties -> smaller index first)
    unsigned long long key =
        ((unsigned long long)__float_as_uint(nu) << 10) | (unsigned int)(NN - 1 - i);
    // k = 2..32 fully in-warp
    #pragma unroll
    for (int k = 2; k <= 32; k <<= 1) {
        bool up_ = ((i & k) == 0);
        #pragma unroll
        for (int j = k >> 1; j >= 1; j >>= 1) {
            unsigned long long other = __shfl_xor_sync(~0u, key, j);
            bool lower = ((i & j) == 0);
            bool keepMax = (up_ == lower);
            key = keepMax ? (key > other ? key : other) : (key < other ? key : other);
        }
    }
    s_sk[i] = key;
    __syncthreads();
    for (int k = 64; k <= NN; k <<= 1) {
        for (int j = k >> 1; j >= 32; j >>= 1) {
            int ixj = i ^ j;
            if (ixj > i) {
                unsigned long long a = s_sk[i], c = s_sk[ixj];
                bool desc = ((i & k) == 0);
                if (desc ? (a < c) : (a > c)) { s_sk[i] = c; s_sk[ixj] = a; }
            }
            __syncthreads();
        }
        key = s_sk[i];
        bool up_ = ((i & k) == 0);
        #pragma unroll
        for (int j = 16; j >= 1; j >>= 1) {
            unsigned long long other = __shfl_xor_sync(~0u, key, j);
            bool lower = ((i & j) == 0);
            bool keepMax = (up_ == lower);
            key = keepMax ? (key > other ? key : other) : (key < other ? key : other);
        }
        s_sk[i] = key;
        __syncthreads();
    }

    float snu = __uint_as_float((unsigned int)(key >> 10));
    int oidx = (NN - 1) - (int)(key & (NN - 1));
    float v = 1.f - snu;                 // sorted usage (ascending nonusage order)

    // ---- hierarchical product scan (exclusive)
    float p = v;
    #pragma unroll
    for (int off = 1; off < 32; off <<= 1) {
        float t2 = __shfl_up_sync(~0u, p, off);
        if (lane >= off) p *= t2;
    }
    if (lane == 31) s_wp[wid] = p;
    __syncthreads();
    if (wid == 0) {
        float q = s_wp[lane];
        #pragma unroll
        for (int off = 1; off < 32; off <<= 1) {
            float t2 = __shfl_up_sync(~0u, q, off);
            if (lane >= off) q *= t2;
        }
        s_wp[lane] = q;
    }
    __syncthreads();
    float warpPref = (wid == 0) ? 1.f : s_wp[wid - 1];
    float inclPrev = __shfl_up_sync(~0u, p, 1);
    float excl = (lane == 0) ? warpPref : warpPref * inclPrev;
    s_alloc[oidx] = snu * excl;
    __syncthreads();

    // ---- write weights + uv + scalars
    float alloc = s_alloc[i];
    float ag = ag_[b], wg = wg_[b];
    float ww = wg * (ag*alloc + (1.f - ag)*wc);
    g_ww[b*NN + i] = ww;

    float pp = p_prev[b*NN + i];
    float part[8];
    #pragma unroll
    for (int r = 0; r < RR; r++) {
        g_uv[(b*NN + i)*RR + r] = make_float2(uu[r], uu[r]*ww);
        part[r]     = uu[r]*pp;   // c[r]
        part[4 + r] = uu[r]*ww;   // d[r]
    }
    #pragma unroll
    for (int j = 0; j < 8; j++)
        for (int off = 16; off; off >>= 1) part[j] += __shfl_xor_sync(~0u, part[j], off);
    if (lane == 0)
        for (int j = 0; j < 8; j++) s_red8[wid][j] = part[j];
    __syncthreads();
    if (wid == 0 && lane < 8) {
        float sum = 0.f;
        #pragma unroll
        for (int w = 0; w < 32; w++) sum += s_red8[w][lane];
        g_scal[b*8 + lane] = sum;
    }
}

// ------------------- kernel 3: fused memory update + read-key dots ----------
// grid B*8, 256 threads; block = 128 memory rows.
__global__ void __launch_bounds__(256) k_memnew_rcdot(const float* __restrict__ memory,
                                                      const float* __restrict__ erase,
                                                      const float* __restrict__ wv,
                                                      const float* __restrict__ rkeys,
                                                      const float* __restrict__ rstr) {
    __shared__ float s_m[128*65];       // padded new-memory tile
    __shared__ float s_keys[RR][WW];
    __shared__ float s_kn[RR], s_sp[RR];
    __shared__ float s_e[WW], s_v[WW];
    __shared__ float s_ww[128];
    int b  = blockIdx.x >> 3;
    int n0 = (blockIdx.x & 7) * 128;
    int t  = threadIdx.x;

    if (t < 256) s_keys[t >> 6][t & 63] = rkeys[b*RR*WW + t];
    if (t < WW) { s_e[t] = erase[b*WW + t]; s_v[t] = wv[b*WW + t]; }
    if (t < 128) s_ww[t] = g_ww[b*NN + n0 + t];
    __syncthreads();
    if (t < RR) {
        float ss = 0.f;
        #pragma unroll
        for (int c = 0; c < WW; c++) ss += s_keys[t][c]*s_keys[t][c];
        s_kn[t] = sqrtf(ss + EPSF);
        s_sp[t] = softplusf(rstr[b*RR + t]);
    }

    // phase A: memory_new (8 float4 per thread)
    #pragma unroll
    for (int it = 0; it < 8; it++) {
        int q = it*256 + t;
        int row = q >> 4, c4 = q & 15;
        size_t gi = (size_t)(b*NN + n0 + row)*16 + c4;
        float4 mm = ((const float4*)memory)[gi];
        float ww = s_ww[row];
        float4 o;
        o.x = mm.x*(1.f - ww*s_e[4*c4+0]) + ww*s_v[4*c4+0];
        o.y = mm.y*(1.f - ww*s_e[4*c4+1]) + ww*s_v[4*c4+1];
        o.z = mm.z*(1.f - ww*s_e[4*c4+2]) + ww*s_v[4*c4+2];
        o.w = mm.w*(1.f - ww*s_e[4*c4+3]) + ww*s_v[4*c4+3];
        ((float4*)g_mem_new)[gi] = o;
        float* d = s_m + row*65 + c4*4;
        d[0] = o.x; d[1] = o.y; d[2] = o.z; d[3] = o.w;
    }
    __syncthreads();

    // phase B: 4 read-key dots + norm per row (threads 0..127)
    if (t < 128) {
        const float* rw = s_m + t*65;
        float acc0 = 0.f, acc1 = 0.f, acc2 = 0.f, acc3 = 0.f, sq = 0.f;
        #pragma unroll 8
        for (int c = 0; c < WW; c++) {
            float mv = rw[c];
            sq   += mv*mv;
            acc0 += mv*s_keys[0][c];
            acc1 += mv*s_keys[1][c];
            acc2 += mv*s_keys[2][c];
            acc3 += mv*s_keys[3][c];
        }
        float mn = sqrtf(sq + EPSF);
        int n = n0 + t;
        g_rc[(b*RR + 0)*NN + n] = acc0 / (s_kn[0]*mn + EPSF) * s_sp[0];
        g_rc[(b*RR + 1)*NN + n] = acc1 / (s_kn[1]*mn + EPSF) * s_sp[1];
        g_rc[(b*RR + 2)*NN + n] = acc2 / (s_kn[2]*mn + EPSF) * s_sp[2];
        g_rc[(b*RR + 3)*NN + n] = acc3 / (s_kn[3]*mn + EPSF) * s_sp[3];
    }
}

// ------------------- kernel 4: fused link contraction (one pass over L) -----
__global__ void __launch_bounds__(256) k_link(const float* __restrict__ L) {
    extern __shared__ float smem[];
    float* s_L = smem;                              // 128*129 floats
    float2* s_uvr = (float2*)(smem + 128*129);      // 512 float2
    float2* s_uvc = s_uvr + 512;                    // 512 float2
    int b = blockIdx.x >> 3;
    int rb = blockIdx.x & 7;
    int n0 = rb * 128;
    int t = threadIdx.x;

    ((float4*)s_uvr)[t] = ((const float4*)g_uv)[(size_t)(b*NN + n0)*2 + t];

    unsigned long long facc[RR] = {0ull,0ull,0ull,0ull};

    for (int s = 0; s < 8; s++) {
        __syncthreads();
        #pragma unroll
        for (int k = 0; k < 16; k++) {
            int q = k*256 + t;
            int row = q >> 5, c4 = q & 31;
            float4 v = ((const float4*)L)[(size_t)(b*NN + n0 + row)*256 + s*32 + c4];
            float* d = s_L + row*129 + c4*4;
            d[0] = v.x; d[1] = v.y; d[2] = v.z; d[3] = v.w;
        }
        ((float4*)s_uvc)[t] = ((const float4*)g_uv)[(size_t)(b*NN + s*128)*2 + t];
        __syncthreads();

        if (t < 128) {
            const unsigned long long* uvc = (const unsigned long long*)s_uvc;
            const float* Lr = s_L + t*129;
            #pragma unroll 4
            for (int c = 0; c < 128; c++) {
                float Lv = Lr[c];
                unsigned long long LL = pack2(Lv, Lv);
                fma2(facc[0], LL, uvc[c*4+0]);
                fma2(facc[1], LL, uvc[c*4+1]);
                fma2(facc[2], LL, uvc[c*4+2]);
                fma2(facc[3], LL, uvc[c*4+3]);
            }
        } else {
            int c = t - 128;
            const unsigned long long* uvr = (const unsigned long long*)s_uvr;
            unsigned long long bacc[RR] = {0ull,0ull,0ull,0ull};
            #pragma unroll 4
            for (int m = 0; m < 128; m++) {
                float Lv = s_L[m*129 + c];
                unsigned long long LL = pack2(Lv, Lv);
                fma2(bacc[0], LL, uvr[m*4+0]);
                fma2(bacc[1], LL, uvr[m*4+1]);
                fma2(bacc[2], LL, uvr[m*4+2]);
                fma2(bacc[3], LL, uvr[m*4+3]);
            }
            int gcol = s*128 + c;
            float w = g_ww[b*NN + gcol];
            #pragma unroll
            for (int r = 0; r < RR; r++) {
                float A, Bv; unpack2(bacc[r], A, Bv);
                g_bwdP[(size_t)rb*(BB*RR*NN) + (size_t)(b*RR + r)*NN + gcol] = (1.f - w)*A - Bv;
            }
        }
    }

    if (t < 128) {
        int n = n0 + t;
        float w = g_ww[b*NN + n];
        #pragma unroll
        for (int r = 0; r < RR; r++) {
            float A, Bv; unpack2(facc[r], A, Bv);
            g_fwd[(size_t)(b*RR + r)*NN + n] = (1.f - w)*A - Bv + w*g_scal[b*8 + r];
        }
    }
}

// ------------------- kernel 5: read softmax + read weights + read words -----
__global__ void __launch_bounds__(1024) k_out(const float* __restrict__ p_prev,
                                              const float* __restrict__ rmode,
                                              float* __restrict__ out) {
    __shared__ float s_rw[RR*NN];        // 16KB
    __shared__ float s_acc[16*RR*WW];    // 16KB
    __shared__ float s_red[33];
    __shared__ float s_bm[RR], s_fm[RR], s_cm[RR];
    __shared__ float s_d[RR];
    int b = blockIdx.x, t = threadIdx.x;
    int lane = t & 31, wid = t >> 5;

    if (t < RR) {
        const float* rm = rmode + (b*RR + t)*3;
        float v0 = rm[0], v1 = rm[1], v2 = rm[2];
        float mx = fmaxf(v0, fmaxf(v1, v2));
        float e0 = expf(v0 - mx), e1 = expf(v1 - mx), e2 = expf(v2 - mx);
        float inv = 1.f / (e0 + e1 + e2);
        s_bm[t] = e0*inv; s_fm[t] = e1*inv; s_cm[t] = e2*inv;
        s_d[t]  = g_scal[b*8 + 4 + t];
    }
    __syncthreads();

    float pp = p_prev[b*NN + t];
    // per-r: softmax(rc sharp) + combine into read weights
    for (int r = 0; r < RR; r++) {
        float sharp = g_rc[(b*RR + r)*NN + t];
        float m = sharp;
        for (int off = 16; off; off >>= 1) m = fmaxf(m, __shfl_xor_sync(~0u, m, off));
        if (lane == 0) s_red[wid] = m;
        __syncthreads();
        if (wid == 0) {
            float mm = s_red[lane];
            for (int off = 16; off; off >>= 1) mm = fmaxf(mm, __shfl_xor_sync(~0u, mm, off));
            if (lane == 0) s_red[32] = mm;
        }
        __syncthreads();
        float e = expf(sharp - s_red[32]);
        float s = e;
        for (int off = 16; off; off >>= 1) s += __shfl_xor_sync(~0u, s, off);
        __syncthreads();
        if (lane == 0) s_red[wid] = s;
        __syncthreads();
        if (wid == 0) {
            float ss = s_red[lane];
            for (int off = 16; off; off >>= 1) ss += __shfl_xor_sync(~0u, ss, off);
            if (lane == 0) s_red[32] = ss;
        }
        __syncthreads();
        float rc = e / s_red[32];

        float bsum = 0.f;
        #pragma unroll
        for (int rb2 = 0; rb2 < 8; rb2++)
            bsum += g_bwdP[(size_t)rb2*(BB*RR*NN) + (size_t)(b*RR + r)*NN + t];
        float bwd = bsum + pp*s_d[r];
        float fwd = g_fwd[(size_t)(b*RR + r)*NN + t];
        s_rw[r*NN + t] = s_cm[r]*rc + s_fm[r]*fwd + s_bm[r]*bwd;
        __syncthreads();
    }

    // GEMV: read_words[r][c] = sum_n rw[r][n] * mem_new[n][c]
    int c = t & 63, sl = t >> 6;         // 16 slices of 64 n
    float acc0 = 0.f, acc1 = 0.f, acc2 = 0.f, acc3 = 0.f;
    #pragma unroll 4
    for (int nn = 0; nn < 64; nn++) {
        int n = sl*64 + nn;
        float mv = g_mem_new[((size_t)b*NN + n)*WW + c];
        acc0 += s_rw[0*NN + n]*mv;
        acc1 += s_rw[1*NN + n]*mv;
        acc2 += s_rw[2*NN + n]*mv;
        acc3 += s_rw[3*NN + n]*mv;
    }
    s_acc[(sl*RR + 0)*WW + c] = acc0;
    s_acc[(sl*RR + 1)*WW + c] = acc1;
    s_acc[(sl*RR + 2)*WW + c] = acc2;
    s_acc[(sl*RR + 3)*WW + c] = acc3;
    __syncthreads();
    if (t < RR*WW) {
        int r = t >> 6, cc = t & 63;
        float s = 0.f;
        #pragma unroll
        for (int sl2 = 0; sl2 < 16; sl2++) s += s_acc[(sl2*RR + r)*WW + cc];
        out[(b*RR + r)*WW + cc] = s;
    }
}

// ------------------- launch -------------------------------------------------
extern "C" void kernel_launch(void* const* d_in, const int* in_sizes, int n_in,
                              void* d_out, int out_size) {
    const float* memory   = (const float*)d_in[0];
    const float* usage_p  = (const float*)d_in[1];
    const float* link_p   = (const float*)d_in[2];
    const float* prec_p   = (const float*)d_in[3];
    const float* rwp      = (const float*)d_in[4];
    const float* wwp      = (const float*)d_in[5];
    const float* rkeys    = (const float*)d_in[6];
    const float* rstr     = (const float*)d_in[7];
    const float* wkeys    = (const float*)d_in[8];
    const float* wstr     = (const float*)d_in[9];
    const float* erase    = (const float*)d_in[10];
    const float* wvec     = (const float*)d_in[11];
    const float* fgate    = (const float*)d_in[12];
    const float* agate    = (const float*)d_in[13];
    const float* wgate    = (const float*)d_in[14];
    const float* rmode    = (const float*)d_in[15];
    float* out = (float*)d_out;

    const int link_smem = (128*129)*4 + 512*8 + 512*8;   // 74240 bytes
    cudaFuncSetAttribute(k_link, cudaFuncAttributeMaxDynamicSharedMemorySize, link_smem);

    k_wdot<<<BB*8, 128>>>(memory, wkeys, wstr);
    k_alloc<<<BB, 1024>>>(usage_p, wwp, fgate, rwp, prec_p, agate, wgate);
    k_memnew_rcdot<<<BB*8, 256>>>(memory, erase, wvec, rkeys, rstr);
    k_link<<<BB*8, 256, link_smem>>>(link_p);
    k_out<<<BB, 1024>>>(prec_p, rmode, out);
}